// round 1
// baseline (speedup 1.0000x reference)
#include <cuda_runtime.h>
#include <cstdint>

// Problem shape (fixed for this problem instance)
#define B_    8
#define S_    1024
#define D_    1024
#define H_    4096
#define MTOK  (B_ * S_)          // 8192 rows (tokens)
#define KSEL  1048576u           // min(TOP_K*S, S*H) = 1024*1024
#define CAP   (1u << 21)         // candidate buffer capacity per batch (2M)

// ---------------- static device scratch (no allocs allowed) ----------------
__device__ float    g_S1[(size_t)MTOK * H_];   // relu(X@W1^T+b1)          128MB
__device__ float    g_S2[(size_t)MTOK * H_];   // scores                    128MB
__device__ float    g_Hb[(size_t)MTOK * H_];   // silu hidden               128MB
__device__ unsigned g_maxu[B_ * H_];           // per-(b,h) max (monotone key)
__device__ unsigned g_hist[B_ * 4096];         // per-batch 12-bit histogram
__device__ unsigned g_cand[(size_t)B_ * CAP];  // threshold-bin candidates   64MB
__device__ unsigned g_cnt[B_];
__device__ unsigned g_bstar[B_];
__device__ unsigned g_rankk[B_];
__device__ unsigned g_thr[B_];

__device__ __forceinline__ unsigned mono(float f) {
    unsigned u = __float_as_uint(f);
    return (u & 0x80000000u) ? ~u : (u | 0x80000000u);
}

// ---------------- aux kernels ----------------
__global__ void zero_aux_kernel() {
    int i = blockIdx.x * blockDim.x + threadIdx.x;
    if (i < B_ * H_) { g_maxu[i] = 0u; }
    if (i < B_ * 4096) { g_hist[i] = 0u; }
    if (i < B_) { g_cnt[i] = 0u; }
}

// Find the 12-bit bin containing the k-th largest value per batch.
__global__ void find_bin_kernel() {
    int b = blockIdx.x;
    __shared__ unsigned s[4096];
    for (int i = threadIdx.x; i < 4096; i += blockDim.x) s[i] = g_hist[b * 4096 + i];
    __syncthreads();
    if (threadIdx.x == 0) {
        unsigned cum = 0;
        for (int bin = 4095; bin >= 0; --bin) {
            unsigned c = s[bin];
            if (cum + c >= KSEL) {
                g_bstar[b] = (unsigned)bin;
                g_rankk[b] = KSEL - cum;   // 1-based rank within this bin
                break;
            }
            cum += c;
        }
    }
}

// Collect all elements whose top-12 bits match the threshold bin.
__global__ void collect_kernel() {
    const int total = MTOK * H_;               // 33,554,432 (fits int)
    for (int idx = blockIdx.x * blockDim.x + threadIdx.x; idx < total;
         idx += gridDim.x * blockDim.x) {
        int b = idx >> 22;                     // S_*H_ = 2^22 per batch
        unsigned u = mono(g_S2[idx]);
        if ((u >> 20) == g_bstar[b]) {
            unsigned p = atomicAdd(&g_cnt[b], 1u);
            if (p < CAP) g_cand[(size_t)b * CAP + p] = u;
        }
    }
}

// Exact radix select over candidates: refine bits [19:12], [11:4], [3:0].
__global__ void select_kernel() {
    int b = blockIdx.x;
    int tid = threadIdx.x;
    int wid = tid >> 5;
    __shared__ unsigned wh[8][256];
    __shared__ unsigned sh_sel, sh_r;

    unsigned n = g_cnt[b]; if (n > CAP) n = CAP;
    unsigned r = g_rankk[b];
    unsigned prefix = g_bstar[b] << 20;
    unsigned pmask = 0xFFF00000u;
    const unsigned* cd = &g_cand[(size_t)b * CAP];

    const int shifts[3] = {12, 4, 0};
    const int nbits[3]  = {8, 8, 4};

    for (int round = 0; round < 3; ++round) {
        int sh = shifts[round];
        unsigned fmask = (1u << nbits[round]) - 1u;
        for (int i = tid; i < 8 * 256; i += blockDim.x) ((unsigned*)wh)[i] = 0u;
        __syncthreads();
        for (unsigned i = tid; i < n; i += blockDim.x) {
            unsigned u = cd[i];
            if ((u & pmask) == prefix) atomicAdd(&wh[wid][(u >> sh) & fmask], 1u);
        }
        __syncthreads();
        if (tid == 0) {
            unsigned cum = 0;
            for (int bin = (int)fmask; bin >= 0; --bin) {
                unsigned c = 0;
                for (int w = 0; w < 8; ++w) c += wh[w][bin];
                if (cum + c >= r) { sh_sel = (unsigned)bin; sh_r = r - cum; break; }
                cum += c;
            }
        }
        __syncthreads();
        prefix |= sh_sel << sh;
        pmask  |= fmask << sh;
        r = sh_r;
        __syncthreads();
    }
    if (tid == 0) g_thr[b] = prefix;   // exact k-th largest (monotone u32)
}

// ---------------- tiled fp32 SGEMM: C = A[M,K] * Bw[N,K]^T (+epilogues) ----
// MODE 0: relu(acc+bias) -> C                  (gate layer 1)
// MODE 1: acc+bias -> C, + per-(b,h) max + 12-bit histogram (gate layer 2)
// MODE 2: B rows selected mod_w/up_w by mask; silu(acc+bias_sel) -> C
// MODE 3: acc+bias -> C                        (down projection)
#define BM 128
#define BN 128
#define BKT 16

template <int MODE>
__global__ __launch_bounds__(256, 2)
void gemm_k(const float* __restrict__ A, const float* __restrict__ Bw,
            const float* __restrict__ Bw2, const float* __restrict__ bias,
            const float* __restrict__ bias2, float* __restrict__ C,
            int M, int N, int K) {
    __shared__ float As[BKT][BM + 4];
    __shared__ float Bs[BKT][BN + 4];
    __shared__ unsigned shist[(MODE == 1) ? 4096 : 1];

    const int tid = threadIdx.x;
    const int tx = tid & 15, ty = tid >> 4;
    const int m0 = blockIdx.y * BM, n0 = blockIdx.x * BN;
    const int batch = m0 >> 10;    // S_ = 1024 rows per batch, tiles never straddle

    if constexpr (MODE == 1) {
        for (int i = tid; i < 4096; i += 256) shist[i] = 0u;
    }

    const int lr = tid >> 2;            // 0..63
    const int lk = (tid & 3) << 2;      // 0,4,8,12

    const float* aptr0 = A + (size_t)(m0 + lr) * K + lk;
    const float* aptr1 = A + (size_t)(m0 + lr + 64) * K + lk;

    const float* bp0;
    const float* bp1;
    if constexpr (MODE == 2) {
        int nr0 = n0 + lr, nr1 = n0 + lr + 64;
        unsigned thr = g_thr[batch];
        bp0 = ((g_maxu[batch * H_ + nr0] >= thr) ? Bw2 : Bw) + (size_t)nr0 * K + lk;
        bp1 = ((g_maxu[batch * H_ + nr1] >= thr) ? Bw2 : Bw) + (size_t)nr1 * K + lk;
    } else {
        bp0 = Bw + (size_t)(n0 + lr) * K + lk;
        bp1 = Bw + (size_t)(n0 + lr + 64) * K + lk;
    }

    float acc[8][8];
#pragma unroll
    for (int i = 0; i < 8; i++)
#pragma unroll
        for (int j = 0; j < 8; j++) acc[i][j] = 0.f;

    float4 sa0 = *(const float4*)aptr0;
    float4 sa1 = *(const float4*)aptr1;
    float4 sb0 = *(const float4*)bp0;
    float4 sb1 = *(const float4*)bp1;

    const int nk = K / BKT;
    for (int t = 0; t < nk; ++t) {
        As[lk + 0][lr] = sa0.x; As[lk + 1][lr] = sa0.y;
        As[lk + 2][lr] = sa0.z; As[lk + 3][lr] = sa0.w;
        As[lk + 0][lr + 64] = sa1.x; As[lk + 1][lr + 64] = sa1.y;
        As[lk + 2][lr + 64] = sa1.z; As[lk + 3][lr + 64] = sa1.w;
        Bs[lk + 0][lr] = sb0.x; Bs[lk + 1][lr] = sb0.y;
        Bs[lk + 2][lr] = sb0.z; Bs[lk + 3][lr] = sb0.w;
        Bs[lk + 0][lr + 64] = sb1.x; Bs[lk + 1][lr + 64] = sb1.y;
        Bs[lk + 2][lr + 64] = sb1.z; Bs[lk + 3][lr + 64] = sb1.w;
        __syncthreads();

        if (t + 1 < nk) {
            int off = (t + 1) * BKT;
            sa0 = *(const float4*)(aptr0 + off);
            sa1 = *(const float4*)(aptr1 + off);
            sb0 = *(const float4*)(bp0 + off);
            sb1 = *(const float4*)(bp1 + off);
        }

#pragma unroll
        for (int k = 0; k < BKT; ++k) {
            float4 a0 = *(const float4*)&As[k][ty * 8];
            float4 a1 = *(const float4*)&As[k][ty * 8 + 4];
            float4 b0 = *(const float4*)&Bs[k][tx * 8];
            float4 b1 = *(const float4*)&Bs[k][tx * 8 + 4];
            float af[8] = {a0.x, a0.y, a0.z, a0.w, a1.x, a1.y, a1.z, a1.w};
            float bf[8] = {b0.x, b0.y, b0.z, b0.w, b1.x, b1.y, b1.z, b1.w};
#pragma unroll
            for (int i = 0; i < 8; i++)
#pragma unroll
                for (int j = 0; j < 8; j++) acc[i][j] += af[i] * bf[j];
        }
        __syncthreads();
    }

    const int row0 = m0 + ty * 8;
    const int col0 = n0 + tx * 8;

    if constexpr (MODE == 0 || MODE == 3) {
#pragma unroll
        for (int i = 0; i < 8; i++) {
            float o[8];
#pragma unroll
            for (int j = 0; j < 8; j++) {
                float v = acc[i][j] + bias[col0 + j];
                if (MODE == 0) v = fmaxf(v, 0.f);
                o[j] = v;
            }
            *(float4*)&C[(size_t)(row0 + i) * N + col0] = make_float4(o[0], o[1], o[2], o[3]);
            *(float4*)&C[(size_t)(row0 + i) * N + col0 + 4] = make_float4(o[4], o[5], o[6], o[7]);
        }
    } else if constexpr (MODE == 1) {
        unsigned cm[8] = {0, 0, 0, 0, 0, 0, 0, 0};
#pragma unroll
        for (int i = 0; i < 8; i++) {
            float o[8];
#pragma unroll
            for (int j = 0; j < 8; j++) {
                float v = acc[i][j] + bias[col0 + j];
                o[j] = v;
                unsigned u = mono(v);
                cm[j] = (u > cm[j]) ? u : cm[j];
                atomicAdd(&shist[u >> 20], 1u);
            }
            *(float4*)&C[(size_t)(row0 + i) * N + col0] = make_float4(o[0], o[1], o[2], o[3]);
            *(float4*)&C[(size_t)(row0 + i) * N + col0 + 4] = make_float4(o[4], o[5], o[6], o[7]);
        }
#pragma unroll
        for (int j = 0; j < 8; j++) atomicMax(&g_maxu[batch * H_ + col0 + j], cm[j]);
        __syncthreads();
        for (int i = tid; i < 4096; i += 256) {
            unsigned c = shist[i];
            if (c) atomicAdd(&g_hist[batch * 4096 + i], c);
        }
    } else {  // MODE == 2 : masked-weight SiLU
        unsigned thr = g_thr[batch];
#pragma unroll
        for (int i = 0; i < 8; i++) {
            float o[8];
#pragma unroll
            for (int j = 0; j < 8; j++) {
                int n = col0 + j;
                bool sel = (g_maxu[batch * H_ + n] >= thr);
                float bv = sel ? bias2[n] : bias[n];
                float x = acc[i][j] + bv;
                o[j] = x / (1.f + __expf(-x));
            }
            *(float4*)&C[(size_t)(row0 + i) * N + col0] = make_float4(o[0], o[1], o[2], o[3]);
            *(float4*)&C[(size_t)(row0 + i) * N + col0 + 4] = make_float4(o[4], o[5], o[6], o[7]);
        }
    }
}

// ---------------- launcher ----------------
extern "C" void kernel_launch(void* const* d_in, const int* in_sizes, int n_in,
                              void* d_out, int out_size) {
    const float* x       = (const float*)d_in[0];   // [B,S,D]
    const float* up_w    = (const float*)d_in[1];   // [H,D]
    const float* up_b    = (const float*)d_in[2];   // [H]
    const float* gate_w1 = (const float*)d_in[3];   // [H,D]
    const float* gate_b1 = (const float*)d_in[4];   // [H]
    const float* gate_w2 = (const float*)d_in[5];   // [H,H]
    const float* gate_b2 = (const float*)d_in[6];   // [H]
    const float* mod_w   = (const float*)d_in[7];   // [H,D]
    const float* mod_b   = (const float*)d_in[8];   // [H]
    const float* down_w  = (const float*)d_in[9];   // [D,H]
    const float* down_b  = (const float*)d_in[10];  // [D]
    float* out = (float*)d_out;

    float* s1; float* s2; float* hb;
    cudaGetSymbolAddress((void**)&s1, g_S1);
    cudaGetSymbolAddress((void**)&s2, g_S2);
    cudaGetSymbolAddress((void**)&hb, g_Hb);

    zero_aux_kernel<<<(B_ * 4096 + 255) / 256, 256>>>();

    dim3 gHH(H_ / BN, MTOK / BM);   // (32, 64)
    dim3 gHD(D_ / BN, MTOK / BM);   // (8, 64)

    // gate layer 1: S1 = relu(X @ W1^T + b1)
    gemm_k<0><<<gHH, 256>>>(x, gate_w1, nullptr, gate_b1, nullptr, s1, MTOK, H_, D_);
    // gate layer 2: S2 = S1 @ W2^T + b2 (+ per-(b,h) max, 12-bit histogram)
    gemm_k<1><<<gHH, 256>>>(s1, gate_w2, nullptr, gate_b2, nullptr, s2, MTOK, H_, H_);
    // exact top-k threshold per batch
    find_bin_kernel<<<B_, 256>>>();
    collect_kernel<<<1184, 256>>>();
    select_kernel<<<B_, 256>>>();
    // masked FFN: Hb = silu(X @ Wsel^T + bsel)
    gemm_k<2><<<gHH, 256>>>(x, up_w, mod_w, up_b, mod_b, hb, MTOK, H_, D_);
    // down projection: out = Hb @ down_w^T + down_b
    gemm_k<3><<<gHD, 256>>>(hb, down_w, nullptr, down_b, nullptr, out, MTOK, D_, H_);

    (void)in_sizes; (void)n_in; (void)out_size;
}

// round 4
// speedup vs baseline: 2.7815x; 2.7815x over previous
#include <cuda_runtime.h>
#include <cuda_bf16.h>
#include <cstdint>

#define B_    8
#define S_    1024
#define D_    1024
#define H_    4096
#define MTOK  (B_ * S_)
#define KSEL  1048576u
#define CAP   (1u << 21)

// ---------------- static device scratch ----------------
__device__ unsigned short g_Xh[(size_t)MTOK * D_], g_Xl[(size_t)MTOK * D_];
__device__ unsigned short g_W1h[(size_t)H_ * D_], g_W1l[(size_t)H_ * D_];
__device__ unsigned short g_W2h[(size_t)H_ * H_], g_W2l[(size_t)H_ * H_];
__device__ unsigned short g_UPh[(size_t)H_ * D_], g_UPl[(size_t)H_ * D_];
__device__ unsigned short g_MDh[(size_t)H_ * D_], g_MDl[(size_t)H_ * D_];
__device__ unsigned short g_DWh[(size_t)D_ * H_], g_DWl[(size_t)D_ * H_];
__device__ unsigned short g_S1h[(size_t)MTOK * H_], g_S1l[(size_t)MTOK * H_];
__device__ unsigned short g_Hbh[(size_t)MTOK * H_], g_Hbl[(size_t)MTOK * H_];
__device__ float    g_S2[(size_t)MTOK * H_];
__device__ unsigned g_maxu[B_ * H_];
__device__ unsigned g_hist[B_ * 4096];
__device__ unsigned g_cand[(size_t)B_ * CAP];
__device__ unsigned g_cnt[B_], g_bstar[B_], g_rankk[B_], g_thr[B_];

__device__ __forceinline__ unsigned mono(float f) {
    unsigned u = __float_as_uint(f);
    return (u & 0x80000000u) ? ~u : (u | 0x80000000u);
}
__device__ __forceinline__ uint32_t smem_u32(const void* p) {
    uint32_t a;
    asm("{ .reg .u64 t; cvta.to.shared.u64 t, %1; cvt.u32.u64 %0, t; }" : "=r"(a) : "l"(p));
    return a;
}
__device__ __forceinline__ void cp16(uint32_t dst, const void* src) {
    asm volatile("cp.async.cg.shared.global [%0], [%1], 16;" :: "r"(dst), "l"(src) : "memory");
}
#define CP_COMMIT() asm volatile("cp.async.commit_group;" ::: "memory")
#define CP_WAIT1()  asm volatile("cp.async.wait_group 1;" ::: "memory")
#define CP_WAIT0()  asm volatile("cp.async.wait_group 0;" ::: "memory")

#define LDSM4(R, addr) \
    asm volatile("ldmatrix.sync.aligned.m8n8.x4.shared.b16 {%0,%1,%2,%3}, [%4];" \
                 : "=r"((R)[0]), "=r"((R)[1]), "=r"((R)[2]), "=r"((R)[3]) : "r"(addr))

#define MMA_BF16(c, a, b0v, b1v) \
    asm volatile("mma.sync.aligned.m16n8k16.row.col.f32.bf16.bf16.f32 " \
                 "{%0,%1,%2,%3},{%4,%5,%6,%7},{%8,%9},{%0,%1,%2,%3};" \
                 : "+f"((c)[0]), "+f"((c)[1]), "+f"((c)[2]), "+f"((c)[3]) \
                 : "r"((a)[0]), "r"((a)[1]), "r"((a)[2]), "r"((a)[3]), \
                   "r"(b0v), "r"(b1v))

// ---------------- fp32 -> bf16 hi/lo split ----------------
__global__ void split_kernel(const float* __restrict__ s, unsigned short* __restrict__ h,
                             unsigned short* __restrict__ l, size_t n4) {
    size_t stride = (size_t)gridDim.x * blockDim.x;
    for (size_t i = (size_t)blockIdx.x * blockDim.x + threadIdx.x; i < n4; i += stride) {
        float4 v = ((const float4*)s)[i];
        __nv_bfloat16 h0 = __float2bfloat16_rn(v.x), h1 = __float2bfloat16_rn(v.y);
        __nv_bfloat16 h2 = __float2bfloat16_rn(v.z), h3 = __float2bfloat16_rn(v.w);
        __nv_bfloat16 l0 = __float2bfloat16_rn(v.x - __bfloat162float(h0));
        __nv_bfloat16 l1 = __float2bfloat16_rn(v.y - __bfloat162float(h1));
        __nv_bfloat16 l2 = __float2bfloat16_rn(v.z - __bfloat162float(h2));
        __nv_bfloat16 l3 = __float2bfloat16_rn(v.w - __bfloat162float(h3));
        uint2 hv, lv;
        hv.x = (uint32_t)__bfloat16_as_ushort(h0) | ((uint32_t)__bfloat16_as_ushort(h1) << 16);
        hv.y = (uint32_t)__bfloat16_as_ushort(h2) | ((uint32_t)__bfloat16_as_ushort(h3) << 16);
        lv.x = (uint32_t)__bfloat16_as_ushort(l0) | ((uint32_t)__bfloat16_as_ushort(l1) << 16);
        lv.y = (uint32_t)__bfloat16_as_ushort(l2) | ((uint32_t)__bfloat16_as_ushort(l3) << 16);
        ((uint2*)h)[i] = hv;
        ((uint2*)l)[i] = lv;
    }
}

// ---------------- aux kernels (validated round 1) ----------------
__global__ void zero_aux_kernel() {
    int i = blockIdx.x * blockDim.x + threadIdx.x;
    if (i < B_ * H_) g_maxu[i] = 0u;
    if (i < B_ * 4096) g_hist[i] = 0u;
    if (i < B_) g_cnt[i] = 0u;
}

__global__ void find_bin_kernel() {
    int b = blockIdx.x;
    __shared__ unsigned s[4096];
    for (int i = threadIdx.x; i < 4096; i += blockDim.x) s[i] = g_hist[b * 4096 + i];
    __syncthreads();
    if (threadIdx.x == 0) {
        unsigned cum = 0;
        for (int bin = 4095; bin >= 0; --bin) {
            unsigned c = s[bin];
            if (cum + c >= KSEL) { g_bstar[b] = (unsigned)bin; g_rankk[b] = KSEL - cum; break; }
            cum += c;
        }
    }
}

__global__ void collect_kernel() {
    const int total = MTOK * H_;
    for (int idx = blockIdx.x * blockDim.x + threadIdx.x; idx < total;
         idx += gridDim.x * blockDim.x) {
        int b = idx >> 22;
        unsigned u = mono(g_S2[idx]);
        if ((u >> 20) == g_bstar[b]) {
            unsigned p = atomicAdd(&g_cnt[b], 1u);
            if (p < CAP) g_cand[(size_t)b * CAP + p] = u;
        }
    }
}

__global__ void select_kernel() {
    int b = blockIdx.x;
    int tid = threadIdx.x;
    int wid = tid >> 5;
    __shared__ unsigned wh[8][256];
    __shared__ unsigned sh_sel, sh_r;

    unsigned n = g_cnt[b]; if (n > CAP) n = CAP;
    unsigned r = g_rankk[b];
    unsigned prefix = g_bstar[b] << 20;
    unsigned pmask = 0xFFF00000u;
    const unsigned* cd = &g_cand[(size_t)b * CAP];

    const int shifts[3] = {12, 4, 0};
    const int nbits[3]  = {8, 8, 4};
    for (int round = 0; round < 3; ++round) {
        int sh = shifts[round];
        unsigned fmask = (1u << nbits[round]) - 1u;
        for (int i = tid; i < 8 * 256; i += blockDim.x) ((unsigned*)wh)[i] = 0u;
        __syncthreads();
        for (unsigned i = tid; i < n; i += blockDim.x) {
            unsigned u = cd[i];
            if ((u & pmask) == prefix) atomicAdd(&wh[wid][(u >> sh) & fmask], 1u);
        }
        __syncthreads();
        if (tid == 0) {
            unsigned cum = 0;
            for (int bin = (int)fmask; bin >= 0; --bin) {
                unsigned c = 0;
                for (int w = 0; w < 8; ++w) c += wh[w][bin];
                if (cum + c >= r) { sh_sel = (unsigned)bin; sh_r = r - cum; break; }
                cum += c;
            }
        }
        __syncthreads();
        prefix |= sh_sel << sh;
        pmask  |= fmask << sh;
        r = sh_r;
        __syncthreads();
    }
    if (tid == 0) g_thr[b] = prefix;
}

// ---------------- HMMA GEMM: C[M,N] = A[M,K] @ B[N,K]^T (bf16 hi/lo split) ----
// CTA tile 128x128, BK=32, 256 threads (8 warps = 2m x 4n, warp tile 64x32).
// Double-buffered cp.async; XOR-swizzled SMEM; mma.sync.m16n8k16 bf16.
// MODE 0: relu(acc+bias)  -> Ch/Cl bf16 planes         (gate layer 1)
// MODE 1: acc+bias -> Cf fp32 + per-(b,n) max + hist   (gate layer 2)
// MODE 2: B rows sel mod/up by mask; silu -> Ch/Cl     (masked up-proj)
// MODE 3: acc+bias -> Cf fp32                           (down projection)
#define E_STAGE 16384
#define E_AH 0
#define E_AL 4096
#define E_BH 8192
#define E_BL 12288
#define OFF_HIST  65536
#define OFF_BIAS  81920
#define OFF_SEL   82432
#define OFF_CMAX  82944
#define SMEM_TOTAL 83968

__device__ __forceinline__ int swz(int row, int c) {
    return row * 32 + (((c ^ (row & 3) ^ ((row >> 2) & 1))) << 3);
}

template <int MODE>
__global__ void __launch_bounds__(256, 2)
hm_gemm(const unsigned short* __restrict__ Ah, const unsigned short* __restrict__ Al,
        const unsigned short* __restrict__ Bh, const unsigned short* __restrict__ Bl,
        const unsigned short* __restrict__ B2h, const unsigned short* __restrict__ B2l,
        const float* __restrict__ bias, const float* __restrict__ bias2,
        unsigned short* __restrict__ Ch, unsigned short* __restrict__ Cl,
        float* __restrict__ Cf, int N, int K) {
    extern __shared__ char smem[];
    unsigned short* sm16 = (unsigned short*)smem;
    const uint32_t sb = smem_u32(smem);
    const int tid = threadIdx.x, wid = tid >> 5, lane = tid & 31;
    const int wm = wid >> 2, wn = wid & 3;         // 2 x 4 warps
    const int n0 = blockIdx.x * 128, m0 = blockIdx.y * 128;
    const int batch = m0 >> 10;

    float* sbias = (float*)(smem + OFF_BIAS);
    unsigned* ssel = (unsigned*)(smem + OFF_SEL);
    unsigned* scol = (unsigned*)(smem + OFF_CMAX);
    unsigned* shist = (unsigned*)(smem + OFF_HIST);

    if (tid < 128) {
        float bv = bias[n0 + tid];
        if constexpr (MODE == 2) {
            unsigned sel = (g_maxu[batch * H_ + n0 + tid] >= g_thr[batch]) ? 1u : 0u;
            ssel[tid] = sel;
            if (sel) bv = bias2[n0 + tid];
        }
        sbias[tid] = bv;
        if constexpr (MODE == 1) scol[tid] = 0u;
    }
    if constexpr (MODE == 1) {
        for (int i = tid; i < 4096; i += 256) shist[i] = 0u;
    }
    __syncthreads();

    const int nk = K >> 5;

    // cp.async stage fill: 4 planes x 512 chunks of 16B; thread does q=tid, tid+256 per plane
    auto loads = [&](int t) {
        const int stg = (t & 1) * E_STAGE;
        const int k0 = t << 5;
#pragma unroll
        for (int it = 0; it < 2; it++) {
            int q = tid + (it << 8);
            int row = q >> 2, c = q & 3;
            uint32_t so = (uint32_t)(stg + swz(row, c)) * 2;
            size_t aoff = (size_t)(m0 + row) * K + k0 + (c << 3);
            cp16(sb + so + E_AH * 2, Ah + aoff);
            cp16(sb + so + E_AL * 2, Al + aoff);
            const unsigned short* bh = Bh;
            const unsigned short* bl = Bl;
            if constexpr (MODE == 2) {
                if (ssel[row]) { bh = B2h; bl = B2l; }
            }
            size_t boff = (size_t)(n0 + row) * K + k0 + (c << 3);
            cp16(sb + so + E_BH * 2, bh + boff);
            cp16(sb + so + E_BL * 2, bl + boff);
        }
        CP_COMMIT();
    };

    float acc[4][4][4];
#pragma unroll
    for (int i = 0; i < 4; i++)
#pragma unroll
        for (int j = 0; j < 4; j++)
#pragma unroll
            for (int r = 0; r < 4; r++) acc[i][j][r] = 0.f;

    // ldmatrix lane addressing (rows/chunk-cols within tile)
    const int a_row = wm * 64 + (lane & 15);
    const int a_cg  = lane >> 4;                       // 0/1 -> k-chunk half
    const int b_row = wn * 32 + ((lane >> 4) << 3) + (lane & 7);
    const int b_cg  = (lane >> 3) & 1;

    loads(0);
    for (int t = 0; t < nk; t++) {
        if (t + 1 < nk) { loads(t + 1); CP_WAIT1(); } else { CP_WAIT0(); }
        __syncthreads();
        const int stg = (t & 1) * E_STAGE;
#pragma unroll
        for (int kk = 0; kk < 2; kk++) {
            const int ac = kk * 2 + a_cg;
            const int bc = kk * 2 + b_cg;
            uint32_t ah[4][4], bhf[2][4];
#pragma unroll
            for (int mi = 0; mi < 4; mi++) {
                uint32_t ad = sb + (uint32_t)(stg + E_AH + swz(a_row + mi * 16, ac)) * 2;
                LDSM4(ah[mi], ad);
            }
#pragma unroll
            for (int g = 0; g < 2; g++) {
                uint32_t bd = sb + (uint32_t)(stg + E_BH + swz(b_row + g * 16, bc)) * 2;
                LDSM4(bhf[g], bd);
            }
#pragma unroll
            for (int mi = 0; mi < 4; mi++)
#pragma unroll
                for (int ni = 0; ni < 4; ni++)
                    MMA_BF16(acc[mi][ni], ah[mi], bhf[ni >> 1][(ni & 1) * 2],
                             bhf[ni >> 1][(ni & 1) * 2 + 1]);
            {   // Ah x Bl
                uint32_t blf[2][4];
#pragma unroll
                for (int g = 0; g < 2; g++) {
                    uint32_t bd = sb + (uint32_t)(stg + E_BL + swz(b_row + g * 16, bc)) * 2;
                    LDSM4(blf[g], bd);
                }
#pragma unroll
                for (int mi = 0; mi < 4; mi++)
#pragma unroll
                    for (int ni = 0; ni < 4; ni++)
                        MMA_BF16(acc[mi][ni], ah[mi], blf[ni >> 1][(ni & 1) * 2],
                                 blf[ni >> 1][(ni & 1) * 2 + 1]);
            }
            {   // Al x Bh
                uint32_t al[4][4];
#pragma unroll
                for (int mi = 0; mi < 4; mi++) {
                    uint32_t ad = sb + (uint32_t)(stg + E_AL + swz(a_row + mi * 16, ac)) * 2;
                    LDSM4(al[mi], ad);
                }
#pragma unroll
                for (int mi = 0; mi < 4; mi++)
#pragma unroll
                    for (int ni = 0; ni < 4; ni++)
                        MMA_BF16(acc[mi][ni], al[mi], bhf[ni >> 1][(ni & 1) * 2],
                                 bhf[ni >> 1][(ni & 1) * 2 + 1]);
            }
        }
        __syncthreads();
    }
    (void)sm16;

    // ---------------- epilogue (register fragments) ----------------
    const int er0 = m0 + wm * 64 + (lane >> 2);
    const int ec0 = n0 + wn * 32 + (lane & 3) * 2;
    unsigned my_cmax[4][2];
    if constexpr (MODE == 1) {
#pragma unroll
        for (int ni = 0; ni < 4; ni++) { my_cmax[ni][0] = 0u; my_cmax[ni][1] = 0u; }
    }

#pragma unroll
    for (int mi = 0; mi < 4; mi++) {
#pragma unroll
        for (int ni = 0; ni < 4; ni++) {
#pragma unroll
            for (int half = 0; half < 2; half++) {     // regs {0,1} row, {2,3} row+8
                int row = er0 + mi * 16 + half * 8;
                int col = ec0 + ni * 8;
                float v0 = acc[mi][ni][half * 2 + 0] + sbias[col - n0];
                float v1 = acc[mi][ni][half * 2 + 1] + sbias[col - n0 + 1];
                if constexpr (MODE == 0) {
                    v0 = fmaxf(v0, 0.f); v1 = fmaxf(v1, 0.f);
                } else if constexpr (MODE == 2) {
                    v0 = v0 / (1.f + __expf(-v0));
                    v1 = v1 / (1.f + __expf(-v1));
                }
                if constexpr (MODE == 0 || MODE == 2) {
                    __nv_bfloat16 h0 = __float2bfloat16_rn(v0), h1 = __float2bfloat16_rn(v1);
                    __nv_bfloat16 l0 = __float2bfloat16_rn(v0 - __bfloat162float(h0));
                    __nv_bfloat16 l1 = __float2bfloat16_rn(v1 - __bfloat162float(h1));
                    uint32_t hv = (uint32_t)__bfloat16_as_ushort(h0) |
                                  ((uint32_t)__bfloat16_as_ushort(h1) << 16);
                    uint32_t lv = (uint32_t)__bfloat16_as_ushort(l0) |
                                  ((uint32_t)__bfloat16_as_ushort(l1) << 16);
                    size_t off = (size_t)row * N + col;
                    *(uint32_t*)(Ch + off) = hv;
                    *(uint32_t*)(Cl + off) = lv;
                } else {
                    if constexpr (MODE == 1) {
                        unsigned u0 = mono(v0), u1 = mono(v1);
                        atomicAdd(&shist[u0 >> 20], 1u);
                        atomicAdd(&shist[u1 >> 20], 1u);
                        if (u0 > my_cmax[ni][0]) my_cmax[ni][0] = u0;
                        if (u1 > my_cmax[ni][1]) my_cmax[ni][1] = u1;
                    }
                    float2 o = make_float2(v0, v1);
                    *(float2*)(Cf + (size_t)row * N + col) = o;
                }
            }
        }
    }

    if constexpr (MODE == 1) {
#pragma unroll
        for (int ni = 0; ni < 4; ni++) {
            int c = wn * 32 + ni * 8 + (lane & 3) * 2;
            atomicMax(&scol[c], my_cmax[ni][0]);
            atomicMax(&scol[c + 1], my_cmax[ni][1]);
        }
        __syncthreads();
        if (tid < 128) atomicMax(&g_maxu[batch * H_ + n0 + tid], scol[tid]);
        for (int i = tid; i < 4096; i += 256) {
            unsigned c = shist[i];
            if (c) atomicAdd(&g_hist[batch * 4096 + i], c);
        }
    }
}

// ---------------- launcher ----------------
extern "C" void kernel_launch(void* const* d_in, const int* in_sizes, int n_in,
                              void* d_out, int out_size) {
    const float* x       = (const float*)d_in[0];
    const float* up_w    = (const float*)d_in[1];
    const float* up_b    = (const float*)d_in[2];
    const float* gate_w1 = (const float*)d_in[3];
    const float* gate_b1 = (const float*)d_in[4];
    const float* gate_w2 = (const float*)d_in[5];
    const float* gate_b2 = (const float*)d_in[6];
    const float* mod_w   = (const float*)d_in[7];
    const float* mod_b   = (const float*)d_in[8];
    const float* down_w  = (const float*)d_in[9];
    const float* down_b  = (const float*)d_in[10];
    float* out = (float*)d_out;

    unsigned short *xh, *xl, *w1h, *w1l, *w2h, *w2l, *uph, *upl, *mdh, *mdl, *dwh, *dwl;
    unsigned short *s1h, *s1l, *hbh, *hbl;
    float* s2;
    cudaGetSymbolAddress((void**)&xh, g_Xh);   cudaGetSymbolAddress((void**)&xl, g_Xl);
    cudaGetSymbolAddress((void**)&w1h, g_W1h); cudaGetSymbolAddress((void**)&w1l, g_W1l);
    cudaGetSymbolAddress((void**)&w2h, g_W2h); cudaGetSymbolAddress((void**)&w2l, g_W2l);
    cudaGetSymbolAddress((void**)&uph, g_UPh); cudaGetSymbolAddress((void**)&upl, g_UPl);
    cudaGetSymbolAddress((void**)&mdh, g_MDh); cudaGetSymbolAddress((void**)&mdl, g_MDl);
    cudaGetSymbolAddress((void**)&dwh, g_DWh); cudaGetSymbolAddress((void**)&dwl, g_DWl);
    cudaGetSymbolAddress((void**)&s1h, g_S1h); cudaGetSymbolAddress((void**)&s1l, g_S1l);
    cudaGetSymbolAddress((void**)&hbh, g_Hbh); cudaGetSymbolAddress((void**)&hbl, g_Hbl);
    cudaGetSymbolAddress((void**)&s2, g_S2);

    cudaFuncSetAttribute(hm_gemm<0>, cudaFuncAttributeMaxDynamicSharedMemorySize, SMEM_TOTAL);
    cudaFuncSetAttribute(hm_gemm<1>, cudaFuncAttributeMaxDynamicSharedMemorySize, SMEM_TOTAL);
    cudaFuncSetAttribute(hm_gemm<2>, cudaFuncAttributeMaxDynamicSharedMemorySize, SMEM_TOTAL);
    cudaFuncSetAttribute(hm_gemm<3>, cudaFuncAttributeMaxDynamicSharedMemorySize, SMEM_TOTAL);

    zero_aux_kernel<<<(B_ * 4096 + 255) / 256, 256>>>();

    split_kernel<<<1024, 256>>>(x, xh, xl, (size_t)MTOK * D_ / 4);
    split_kernel<<<1024, 256>>>(gate_w1, w1h, w1l, (size_t)H_ * D_ / 4);
    split_kernel<<<1024, 256>>>(gate_w2, w2h, w2l, (size_t)H_ * H_ / 4);
    split_kernel<<<1024, 256>>>(up_w, uph, upl, (size_t)H_ * D_ / 4);
    split_kernel<<<1024, 256>>>(mod_w, mdh, mdl, (size_t)H_ * D_ / 4);
    split_kernel<<<1024, 256>>>(down_w, dwh, dwl, (size_t)D_ * H_ / 4);

    dim3 gHH(H_ / 128, MTOK / 128);   // (32, 64)
    dim3 gHD(D_ / 128, MTOK / 128);   // (8, 64)

    // gate layer 1: S1 = relu(X @ W1^T + b1) -> hi/lo planes
    hm_gemm<0><<<gHH, 256, SMEM_TOTAL>>>(xh, xl, w1h, w1l, nullptr, nullptr,
                                         gate_b1, nullptr, s1h, s1l, nullptr, H_, D_);
    // gate layer 2: S2 = S1 @ W2^T + b2 (+ max/hist)
    hm_gemm<1><<<gHH, 256, SMEM_TOTAL>>>(s1h, s1l, w2h, w2l, nullptr, nullptr,
                                         gate_b2, nullptr, nullptr, nullptr, s2, H_, H_);
    find_bin_kernel<<<B_, 256>>>();
    collect_kernel<<<1184, 256>>>();
    select_kernel<<<B_, 256>>>();
    // masked up-proj: Hb = silu(X @ Wsel^T + bsel) -> hi/lo planes
    hm_gemm<2><<<gHH, 256, SMEM_TOTAL>>>(xh, xl, uph, upl, mdh, mdl,
                                         up_b, mod_b, hbh, hbl, nullptr, H_, D_);
    // down projection: out = Hb @ down_w^T + down_b
    hm_gemm<3><<<gHD, 256, SMEM_TOTAL>>>(hbh, hbl, dwh, dwl, nullptr, nullptr,
                                         down_b, nullptr, nullptr, nullptr, out, D_, H_);

    (void)in_sizes; (void)n_in; (void)out_size;
}